// round 15
// baseline (speedup 1.0000x reference)
#include <cuda_runtime.h>
#include <cuda_fp16.h>
#include <cstdint>

#define NN   6144
#define INF  512
#define H    8
#define OUTF 512
#define NW   192
#define ECAP 28000.0f
#define NT   (NN / 128)

// ---------------- scratch ----------------
__device__ __align__(16) float2   g_a0a1[H * NN];
__device__ __align__(16) float2   g_ai2[H * NN];           // {u'', u5''}
__device__ __align__(16) uint2    g_ajph[H * NN / 2];      // per j-pair {v01 f16x2, v501 f16x2}
__device__ unsigned g_a1max[H];
__device__ __align__(16) unsigned g_bits[NN * NW];         // nibble-permuted adj bits
__device__ __align__(16) __half   g_hb[H * NN * 64];       // [head][j][d] fp16
__device__ __align__(16) __half   g_xh[NN * INF];
__device__ __align__(16) __half   g_wh[OUTF * INF];

// ---------------- helpers ----------------
__device__ __forceinline__ unsigned pack_f16x2(float hi, float lo) {
    unsigned r;
    asm("cvt.rn.f16x2.f32 %0, %1, %2;" : "=r"(r) : "f"(hi), "f"(lo));
    return r;
}
__device__ __forceinline__ unsigned hmul2(unsigned a, unsigned b) {
    unsigned r;
    asm("mul.rn.f16x2 %0, %1, %2;" : "=r"(r) : "r"(a), "r"(b));
    return r;
}
__device__ __forceinline__ unsigned hmax2(unsigned a, unsigned b) {
    unsigned r;
    asm("max.f16x2 %0, %1, %2;" : "=r"(r) : "r"(a), "r"(b));
    return r;
}
__device__ __forceinline__ uint32_t smem_u32(const void* p) {
    uint32_t a;
    asm("{ .reg .u64 t; cvta.to.shared.u64 t, %1; cvt.u32.u64 %0, t; }" : "=r"(a) : "l"(p));
    return a;
}
__device__ __forceinline__ void cp16(uint32_t dst, const void* src) {
    asm volatile("cp.async.cg.shared.global [%0], [%1], 16;" :: "r"(dst), "l"(src));
}
__device__ __forceinline__ void ldm4(uint32_t addr, unsigned& r0, unsigned& r1,
                                     unsigned& r2, unsigned& r3) {
    asm volatile("ldmatrix.sync.aligned.m8n8.x4.shared.b16 {%0,%1,%2,%3}, [%4];"
                 : "=r"(r0), "=r"(r1), "=r"(r2), "=r"(r3) : "r"(addr));
}
__device__ __forceinline__ void ldm4t(uint32_t addr, unsigned& r0, unsigned& r1,
                                      unsigned& r2, unsigned& r3) {
    asm volatile("ldmatrix.sync.aligned.m8n8.x4.trans.shared.b16 {%0,%1,%2,%3}, [%4];"
                 : "=r"(r0), "=r"(r1), "=r"(r2), "=r"(r3) : "r"(addr));
}
__device__ __forceinline__ void mma16816(float* c, unsigned a0, unsigned a1,
                                         unsigned a2, unsigned a3,
                                         unsigned b0, unsigned b1) {
    asm volatile(
        "mma.sync.aligned.m16n8k16.row.col.f32.f16.f16.f32 "
        "{%0,%1,%2,%3},{%4,%5,%6,%7},{%8,%9},{%0,%1,%2,%3};"
        : "+f"(c[0]), "+f"(c[1]), "+f"(c[2]), "+f"(c[3])
        : "r"(a0), "r"(a1), "r"(a2), "r"(a3), "r"(b0), "r"(b1));
}
__device__ __forceinline__ unsigned fkey(float f) {
    unsigned b = __float_as_uint(f);
    return (b & 0x80000000u) ? ~b : (b | 0x80000000u);
}
__device__ __forceinline__ float funkey(unsigned k) {
    unsigned b = (k & 0x80000000u) ? (k & 0x7fffffffu) : ~k;
    return __uint_as_float(b);
}

// =====================================================================
// Kernel CV: x, W -> fp16; block 0 resets a1max
// =====================================================================
__global__ __launch_bounds__(256) void cvt_kernel(const float* __restrict__ x,
                                                  const float* __restrict__ W) {
    if (blockIdx.x == 0 && threadIdx.x < H) g_a1max[threadIdx.x] = 0u;
    int t = blockIdx.x * 256 + threadIdx.x;
    const int NX = NN * INF / 4;
    const int NWW = OUTF * INF / 4;
    if (t < NX) {
        float4 v = *(const float4*)&x[t * 4];
        *(uint2*)&g_xh[t * 4] = make_uint2(pack_f16x2(v.y, v.x), pack_f16x2(v.w, v.z));
    } else if (t < NX + NWW) {
        int u = t - NX;
        float4 v = *(const float4*)&W[u * 4];
        *(uint2*)&g_wh[u * 4] = make_uint2(pack_f16x2(v.y, v.x), pack_f16x2(v.w, v.z));
    }
}

// =====================================================================
// Kernel A: HMMA h = x@W^T + b (single product), fused a0/a1 epilogue
// =====================================================================
#define GX_ST 15360
#define GX_TOT (2 * GX_ST)

__global__ __launch_bounds__(128, 3) void gemm_h_kernel(
    const float* __restrict__ b, const float* __restrict__ aw) {
    extern __shared__ char gsm[];
    const uint32_t smb = smem_u32(gsm);
    const int tid = threadIdx.x;
    const int wid = tid >> 5;
    const int lane = tid & 31;
    const int m0 = blockIdx.x * 128;
    const int hd = blockIdx.y;
    const int n0 = hd * 64;
    const int wm = wid * 32;

    float acc[8][2][4];
#pragma unroll
    for (int f = 0; f < 8; f++)
#pragma unroll
        for (int m = 0; m < 2; m++)
#pragma unroll
            for (int c = 0; c < 4; c++) acc[f][m][c] = 0.f;

    const int xrow = tid >> 2, xch = tid & 3;
    const int arow = lane & 15, ahalf = lane >> 4;
    const int seg = lane >> 3, lr = lane & 7;
    const int brow_off = (seg >> 1) * 8 + lr;
    const int bkh = seg & 1;

    auto stage = [&](int st, int buf) {
        const int kb = st * 32;
        uint32_t xh = smb + buf * GX_ST;
        uint32_t wh = xh + 10240;
#pragma unroll
        for (int p = 0; p < 4; p++) {
            int row = xrow + p * 32;
            uint32_t d = (uint32_t)(row * 80 + xch * 16);
            cp16(xh + d, &g_xh[(size_t)(m0 + row) * INF + kb + xch * 8]);
        }
#pragma unroll
        for (int p = 0; p < 2; p++) {
            int row = xrow + p * 32;
            uint32_t d = (uint32_t)(row * 80 + xch * 16);
            cp16(wh + d, &g_wh[(size_t)(n0 + row) * INF + kb + xch * 8]);
        }
        asm volatile("cp.async.commit_group;" ::: "memory");
    };

    stage(0, 0);
#pragma unroll 1
    for (int st = 0; st < INF / 32; st++) {
        const int buf = st & 1;
        if (st + 1 < INF / 32) {
            stage(st + 1, buf ^ 1);
            asm volatile("cp.async.wait_group 1;" ::: "memory");
        } else {
            asm volatile("cp.async.wait_group 0;" ::: "memory");
        }
        __syncthreads();
        uint32_t xh = smb + buf * GX_ST;
        uint32_t wh = xh + 10240;
#pragma unroll
        for (int ks = 0; ks < 2; ks++) {
            unsigned axh[2][4];
#pragma unroll
            for (int mf = 0; mf < 2; mf++) {
                ldm4(xh + (wm + mf * 16 + arow) * 80 + ks * 32 + ahalf * 16,
                     axh[mf][0], axh[mf][1], axh[mf][2], axh[mf][3]);
            }
#pragma unroll
            for (int f = 0; f < 4; f++) {
                uint32_t ba = (uint32_t)((f * 16 + brow_off) * 80 + ks * 32 + bkh * 16);
                unsigned bhf[4];
                ldm4(wh + ba, bhf[0], bhf[1], bhf[2], bhf[3]);
#pragma unroll
                for (int g = 0; g < 2; g++) {
#pragma unroll
                    for (int mf = 0; mf < 2; mf++) {
                        mma16816(acc[f * 2 + g][mf],
                                 axh[mf][0], axh[mf][1], axh[mf][2], axh[mf][3],
                                 bhf[2 * g], bhf[2 * g + 1]);
                    }
                }
            }
        }
        __syncthreads();
    }

    const int qc2 = (lane & 3) * 2;
    float dot[4][2];
#pragma unroll
    for (int r = 0; r < 4; r++) { dot[r][0] = 0.f; dot[r][1] = 0.f; }

#pragma unroll
    for (int f = 0; f < 8; f++) {
        int col = f * 8 + qc2;
        float2 bv = *(const float2*)&b[n0 + col];
        float4 awv = *(const float4*)&aw[hd * 128 + col * 2];
#pragma unroll
        for (int mf = 0; mf < 2; mf++) {
            float* C = acc[f][mf];
            int m = m0 + wm + mf * 16 + (lane >> 2);
            float c0 = C[0] + bv.x, c1 = C[1] + bv.y;
            float c2 = C[2] + bv.x, c3 = C[3] + bv.y;
            *(unsigned*)&g_hb[(size_t)(hd * NN + m) * 64 + col] = pack_f16x2(c1, c0);
            *(unsigned*)&g_hb[(size_t)(hd * NN + m + 8) * 64 + col] = pack_f16x2(c3, c2);
            dot[mf * 2][0] += c0 * awv.x + c1 * awv.z;
            dot[mf * 2][1] += c0 * awv.y + c1 * awv.w;
            dot[mf * 2 + 1][0] += c2 * awv.x + c3 * awv.z;
            dot[mf * 2 + 1][1] += c2 * awv.y + c3 * awv.w;
        }
    }
#pragma unroll
    for (int off = 1; off <= 2; off <<= 1)
#pragma unroll
        for (int r = 0; r < 4; r++) {
            dot[r][0] += __shfl_xor_sync(0xffffffffu, dot[r][0], off);
            dot[r][1] += __shfl_xor_sync(0xffffffffu, dot[r][1], off);
        }
    float a1loc = fmaxf(fmaxf(dot[0][1], dot[1][1]), fmaxf(dot[2][1], dot[3][1]));
    if ((lane & 3) == 0) {
        int mbase = m0 + wm + (lane >> 2);
        g_a0a1[hd * NN + mbase] = make_float2(dot[0][0], dot[0][1]);
        g_a0a1[hd * NN + mbase + 8] = make_float2(dot[1][0], dot[1][1]);
        g_a0a1[hd * NN + mbase + 16] = make_float2(dot[2][0], dot[2][1]);
        g_a0a1[hd * NN + mbase + 24] = make_float2(dot[3][0], dot[3][1]);
    }
#pragma unroll
    for (int off = 16; off > 0; off >>= 1)
        a1loc = fmaxf(a1loc, __shfl_xor_sync(0xffffffffu, a1loc, off));
    if (lane == 0) atomicMax(&g_a1max[hd], fkey(a1loc));
}

// =====================================================================
// Kernel B2: scaled tables (both sides fp16-safe)
// =====================================================================
__global__ __launch_bounds__(256) void param2_kernel() {
    int g = blockIdx.x * 256 + threadIdx.x;
    if (g >= H * NN) return;
    int hd = g / NN;
    int i = g - hd * NN;
    float2 a = g_a0a1[g];
    float a1max = funkey(g_a1max[hd]);
    float z = a.x + a1max;
    float sl = (z > 0.f) ? z : 0.2f * z;
    float uh = ECAP * expf(a.x - sl + a1max);
    float u5h = ECAP * expf(0.2f * a.x - sl + 0.2f * a1max);
    g_ai2[g] = make_float2(uh, u5h);
    unsigned short vv = __half_as_ushort(__float2half_rn(expf(a.y - a1max)));
    unsigned short v5 = __half_as_ushort(__float2half_rn(expf(0.2f * (a.y - a1max))));
    unsigned short* dst = (unsigned short*)&g_ajph[hd * (NN / 2) + (i >> 1)];
    int o = i & 1;
    dst[o] = vv;
    dst[2 + o] = v5;
}

// =====================================================================
// Kernel C: adj -> nibble-permuted bitmask (warp-cooperative staging)
// =====================================================================
#define BSWZ(b) ((b) ^ (((b) >> 7 & 7) << 4))

__global__ __launch_bounds__(256) void bits_kernel(const int* __restrict__ adj) {
    __shared__ __align__(16) char stg[8][4096];
    const int tid = threadIdx.x;
    const int wp = tid >> 5;
    const int lane = tid & 31;
    const int w0 = blockIdx.x * 256 + wp * 32;
    const int4* src = (const int4*)(adj + (size_t)w0 * 32);
    char* sm = stg[wp];

#pragma unroll
    for (int c = 0; c < 8; c++) {
        unsigned lb = (unsigned)(c * 512 + lane * 16);
        *(int4*)(sm + BSWZ(lb)) = src[c * 32 + lane];
    }
    __syncwarp();

    int v[32];
#pragma unroll
    for (int c = 0; c < 8; c++) {
        unsigned lb = (unsigned)(lane * 128 + c * 16);
        int4 q = *(const int4*)(sm + BSWZ(lb));
        v[c * 4 + 0] = q.x;
        v[c * 4 + 1] = q.y;
        v[c * 4 + 2] = q.z;
        v[c * 4 + 3] = q.w;
    }
    unsigned word = 0;
#pragma unroll
    for (int hb = 0; hb < 2; hb++) {
#pragma unroll
        for (int n = 0; n < 4; n++) {
            int b = hb * 16 + 2 * n;
            unsigned nib = (unsigned)(v[b] + 2 * v[b + 1] + 4 * v[b + 8] + 8 * v[b + 9]);
            word |= nib << (hb * 16 + n * 4);
        }
    }
    g_bits[w0 + lane] = word;
}

// =====================================================================
// Kernel D: fp16 HMMA attention. occ 4 via register trimming:
// sdst recomputed per use; masks via single base ptr + immediate offsets.
// =====================================================================
#define ONESF16 0x3C003C00u

__global__ __launch_bounds__(128, 4) void attn_kernel(float* __restrict__ out) {
    __shared__ __align__(16) char  sB[2][16384];
    __shared__ __align__(16) uint2 sAjp[2][64];
    __shared__ __align__(16) uint2 sLut[16];

    const int tid = threadIdx.x;
    const int wid = tid >> 5;
    const int lane = tid & 31;
    const int hd = blockIdx.y;
    const int i0 = blockIdx.x * 128;
    const int gr = lane >> 2;
    const int l3 = lane & 3;
    const int mb = wid * 32;

    const uint32_t smB = smem_u32(&sB[0][0]);
    const uint32_t smA = smem_u32(&sAjp[0][0]);

    if (tid < 16) {
        unsigned m01 = ((tid & 1) ? 0x0000FFFFu : 0u) | ((tid & 2) ? 0xFFFF0000u : 0u);
        unsigned m89 = ((tid & 4) ? 0x0000FFFFu : 0u) | ((tid & 8) ? 0xFFFF0000u : 0u);
        sLut[tid] = make_uint2(m01, m89);
    }

    const char* srcH = (const char*)(g_hb + (size_t)hd * NN * 64);
    const uint2* srcA = &g_ajph[hd * (NN / 2)];
    // single mask base; per-r offsets are compile-time immediates (r*8*NW words)
    const unsigned* mbase = g_bits + (size_t)(i0 + mb + gr) * NW;

    const int lg = lane >> 3, lr = lane & 7;
    const int joff = (lg & 1) * 8 + lr;
    const int nsel = lg >> 1;
    const uint32_t lmb = (uint32_t)(joff * 128);
    const int jm = joff & 7;

    unsigned uu[4], u5[4];
#pragma unroll
    for (int r = 0; r < 4; r++) {
        float2 a = g_ai2[hd * NN + i0 + mb + gr + r * 8];
        uu[r] = pack_f16x2(a.x, a.x);
        u5[r] = pack_f16x2(a.y, a.y);
    }

    float accA[8][4], accB[8][4], accSA[4], accSB[4];
#pragma unroll
    for (int n = 0; n < 8; n++)
#pragma unroll
        for (int c = 0; c < 4; c++) { accA[n][c] = 0.f; accB[n][c] = 0.f; }
#pragma unroll
    for (int c = 0; c < 4; c++) { accSA[c] = 0.f; accSB[c] = 0.f; }

    // staging destination (recomputed, not cached in regs)
    auto sdst_of = [&](int p) -> uint32_t {
        int idx = tid + p * 128;
        int sj = idx >> 3, sc = idx & 7;
        return (uint32_t)(sj * 128 + ((sc ^ (sj & 7)) << 4));
    };

    {
#pragma unroll
        for (int p = 0; p < 8; p++)
            cp16(smB + sdst_of(p), srcH + (size_t)(tid + p * 128) * 16);
        if (tid < 32) cp16(smA + tid * 16, srcA + tid * 2);
        asm volatile("cp.async.commit_group;" ::: "memory");
    }

#pragma unroll 1
    for (int jt = 0; jt < NT; jt++) {
        const int s = jt & 1;

        unsigned mw[4][4];
#pragma unroll
        for (int r = 0; r < 4; r++) {
            uint4 t = *(const uint4*)(mbase + r * 8 * NW + jt * 4);
            mw[r][0] = t.x; mw[r][1] = t.y; mw[r][2] = t.z; mw[r][3] = t.w;
        }

        if (jt + 1 < NT) {
            uint32_t bh = smB + (s ^ 1) * 16384;
#pragma unroll
            for (int p = 0; p < 8; p++)
                cp16(bh + sdst_of(p),
                     srcH + (size_t)(jt + 1) * 16384 + (size_t)(tid + p * 128) * 16);
            if (tid < 32) cp16(smA + (s ^ 1) * 512 + tid * 16,
                               srcA + (jt + 1) * 64 + tid * 2);
            asm volatile("cp.async.commit_group;" ::: "memory");
            asm volatile("cp.async.wait_group 1;" ::: "memory");
        } else {
            asm volatile("cp.async.wait_group 0;" ::: "memory");
        }
        __syncthreads();

        const uint32_t bh = smB + s * 16384;
        const uint2* ajb = &sAjp[s][0];

#pragma unroll
        for (int kk = 0; kk < 8; kk++) {
            uint2 va = ajb[kk * 8 + l3];
            uint2 vb = ajb[kk * 8 + 4 + l3];

            unsigned ah[4][2];
#pragma unroll
            for (int r = 0; r < 4; r++) {
                unsigned nib = (mw[r][kk >> 1] >> ((kk & 1) * 16 + l3 * 4)) & 15u;
                uint2 mk = sLut[nib];
                ah[r][0] = hmax2(hmul2(uu[r], va.x), hmul2(u5[r], va.y)) & mk.x;
                ah[r][1] = hmax2(hmul2(uu[r], vb.x), hmul2(u5[r], vb.y)) & mk.y;
            }

            mma16816(accSA, ah[0][0], ah[1][0], ah[0][1], ah[1][1], ONESF16, ONESF16);
            mma16816(accSB, ah[2][0], ah[3][0], ah[2][1], ah[3][1], ONESF16, ONESF16);

#pragma unroll
            for (int nh = 0; nh < 2; nh++) {
                const int nb0 = nh * 32, nb1 = nh * 32 + 16;
                uint32_t a0 = bh + kk * 2048 + lmb + ((((nb0 >> 3) + nsel) ^ jm) << 4);
                uint32_t a1 = bh + kk * 2048 + lmb + ((((nb1 >> 3) + nsel) ^ jm) << 4);
                unsigned t[8];
                ldm4t(a0, t[0], t[1], t[2], t[3]);
                ldm4t(a1, t[4], t[5], t[6], t[7]);
#pragma unroll
                for (int q = 0; q < 4; q++) {
                    mma16816(accA[nh * 4 + q], ah[0][0], ah[1][0], ah[0][1], ah[1][1],
                             t[2 * q], t[2 * q + 1]);
                    mma16816(accB[nh * 4 + q], ah[2][0], ah[3][0], ah[2][1], ah[3][1],
                             t[2 * q], t[2 * q + 1]);
                }
            }
        }
        __syncthreads();
    }

    float inv[4];
    inv[0] = (accSA[0] > 0.f) ? (1.0f / accSA[0]) : 0.f;
    inv[1] = (accSA[2] > 0.f) ? (1.0f / accSA[2]) : 0.f;
    inv[2] = (accSB[0] > 0.f) ? (1.0f / accSB[0]) : 0.f;
    inv[3] = (accSB[2] > 0.f) ? (1.0f / accSB[2]) : 0.f;

    const int qc = l3 * 2;
#pragma unroll
    for (int f = 0; f < 2; f++) {
        float (*A)[4] = f ? accB : accA;
        float* b0 = out + (size_t)(i0 + mb + gr + f * 16) * OUTF + hd * 64 + qc;
        float* b1 = out + (size_t)(i0 + mb + gr + f * 16 + 8) * OUTF + hd * 64 + qc;
        float i0v = inv[f * 2], i1v = inv[f * 2 + 1];
#pragma unroll
        for (int nt = 0; nt < 8; nt++) {
            *(float2*)(b0 + nt * 8) = make_float2(A[nt][0] * i0v, A[nt][1] * i0v);
            *(float2*)(b1 + nt * 8) = make_float2(A[nt][2] * i1v, A[nt][3] * i1v);
        }
    }
}

// =====================================================================
extern "C" void kernel_launch(void* const* d_in, const int* in_sizes, int n_in,
                              void* d_out, int out_size) {
    const float* x = (const float*)d_in[0];
    const int* adj = (const int*)d_in[1];
    const float* W = (const float*)d_in[2];
    const float* b = (const float*)d_in[3];
    const float* aw = (const float*)d_in[4];
    float* out = (float*)d_out;

    cudaFuncSetAttribute(gemm_h_kernel, cudaFuncAttributeMaxDynamicSharedMemorySize,
                         GX_TOT);

    cvt_kernel<<<(NN * INF / 4 + OUTF * INF / 4 + 255) / 256, 256>>>(x, W);
    gemm_h_kernel<<<dim3(NN / 128, H), 128, GX_TOT>>>(b, aw);
    param2_kernel<<<(H * NN + 255) / 256, 256>>>();
    bits_kernel<<<NN * NW / 256, 256>>>(adj);
    attn_kernel<<<dim3(NN / 128, H), 128>>>(out);
}

// round 16
// speedup vs baseline: 1.1048x; 1.1048x over previous
#include <cuda_runtime.h>
#include <cuda_fp16.h>
#include <cstdint>

#define NN   6144
#define INF  512
#define H    8
#define OUTF 512
#define NW   192
#define ECAP 28000.0f
#define NT   (NN / 128)

// ---------------- scratch ----------------
__device__ __align__(16) float2   g_a0a1[H * NN];
__device__ __align__(16) float2   g_ai2[H * NN];           // {u'', u5''}
__device__ __align__(16) uint2    g_ajph[H * NN / 2];      // per j-pair {v01 f16x2, v501 f16x2}
__device__ unsigned g_a1max[H];
__device__ __align__(16) unsigned g_bits[NN * NW];         // nibble-permuted adj bits
__device__ __align__(16) __half   g_hb[H * NN * 64];       // [head][j][d] fp16
__device__ __align__(16) __half   g_xh[NN * INF];
__device__ __align__(16) __half   g_wh[OUTF * INF];

// ---------------- helpers ----------------
__device__ __forceinline__ unsigned pack_f16x2(float hi, float lo) {
    unsigned r;
    asm("cvt.rn.f16x2.f32 %0, %1, %2;" : "=r"(r) : "f"(hi), "f"(lo));
    return r;
}
__device__ __forceinline__ unsigned hmul2(unsigned a, unsigned b) {
    unsigned r;
    asm("mul.rn.f16x2 %0, %1, %2;" : "=r"(r) : "r"(a), "r"(b));
    return r;
}
__device__ __forceinline__ unsigned hmax2(unsigned a, unsigned b) {
    unsigned r;
    asm("max.f16x2 %0, %1, %2;" : "=r"(r) : "r"(a), "r"(b));
    return r;
}
__device__ __forceinline__ uint32_t smem_u32(const void* p) {
    uint32_t a;
    asm("{ .reg .u64 t; cvta.to.shared.u64 t, %1; cvt.u32.u64 %0, t; }" : "=r"(a) : "l"(p));
    return a;
}
__device__ __forceinline__ void cp16(uint32_t dst, const void* src) {
    asm volatile("cp.async.cg.shared.global [%0], [%1], 16;" :: "r"(dst), "l"(src));
}
__device__ __forceinline__ void ldm4(uint32_t addr, unsigned& r0, unsigned& r1,
                                     unsigned& r2, unsigned& r3) {
    asm volatile("ldmatrix.sync.aligned.m8n8.x4.shared.b16 {%0,%1,%2,%3}, [%4];"
                 : "=r"(r0), "=r"(r1), "=r"(r2), "=r"(r3) : "r"(addr));
}
__device__ __forceinline__ void ldm4t(uint32_t addr, unsigned& r0, unsigned& r1,
                                      unsigned& r2, unsigned& r3) {
    asm volatile("ldmatrix.sync.aligned.m8n8.x4.trans.shared.b16 {%0,%1,%2,%3}, [%4];"
                 : "=r"(r0), "=r"(r1), "=r"(r2), "=r"(r3) : "r"(addr));
}
__device__ __forceinline__ void mma16816(float* c, unsigned a0, unsigned a1,
                                         unsigned a2, unsigned a3,
                                         unsigned b0, unsigned b1) {
    asm volatile(
        "mma.sync.aligned.m16n8k16.row.col.f32.f16.f16.f32 "
        "{%0,%1,%2,%3},{%4,%5,%6,%7},{%8,%9},{%0,%1,%2,%3};"
        : "+f"(c[0]), "+f"(c[1]), "+f"(c[2]), "+f"(c[3])
        : "r"(a0), "r"(a1), "r"(a2), "r"(a3), "r"(b0), "r"(b1));
}
__device__ __forceinline__ unsigned fkey(float f) {
    unsigned b = __float_as_uint(f);
    return (b & 0x80000000u) ? ~b : (b | 0x80000000u);
}
__device__ __forceinline__ float funkey(unsigned k) {
    unsigned b = (k & 0x80000000u) ? (k & 0x7fffffffu) : ~k;
    return __uint_as_float(b);
}

// =====================================================================
// Kernel CV: x, W -> fp16; block 0 resets a1max
// =====================================================================
__global__ __launch_bounds__(256) void cvt_kernel(const float* __restrict__ x,
                                                  const float* __restrict__ W) {
    if (blockIdx.x == 0 && threadIdx.x < H) g_a1max[threadIdx.x] = 0u;
    int t = blockIdx.x * 256 + threadIdx.x;
    const int NX = NN * INF / 4;
    const int NWW = OUTF * INF / 4;
    if (t < NX) {
        float4 v = *(const float4*)&x[t * 4];
        *(uint2*)&g_xh[t * 4] = make_uint2(pack_f16x2(v.y, v.x), pack_f16x2(v.w, v.z));
    } else if (t < NX + NWW) {
        int u = t - NX;
        float4 v = *(const float4*)&W[u * 4];
        *(uint2*)&g_wh[u * 4] = make_uint2(pack_f16x2(v.y, v.x), pack_f16x2(v.w, v.z));
    }
}

// =====================================================================
// Kernel A: HMMA h = x@W^T + b (single product), fused a0/a1 epilogue
// =====================================================================
#define GX_ST 15360
#define GX_TOT (2 * GX_ST)

__global__ __launch_bounds__(128, 3) void gemm_h_kernel(
    const float* __restrict__ b, const float* __restrict__ aw) {
    extern __shared__ char gsm[];
    const uint32_t smb = smem_u32(gsm);
    const int tid = threadIdx.x;
    const int wid = tid >> 5;
    const int lane = tid & 31;
    const int m0 = blockIdx.x * 128;
    const int hd = blockIdx.y;
    const int n0 = hd * 64;
    const int wm = wid * 32;

    float acc[8][2][4];
#pragma unroll
    for (int f = 0; f < 8; f++)
#pragma unroll
        for (int m = 0; m < 2; m++)
#pragma unroll
            for (int c = 0; c < 4; c++) acc[f][m][c] = 0.f;

    const int xrow = tid >> 2, xch = tid & 3;
    const int arow = lane & 15, ahalf = lane >> 4;
    const int seg = lane >> 3, lr = lane & 7;
    const int brow_off = (seg >> 1) * 8 + lr;
    const int bkh = seg & 1;

    auto stage = [&](int st, int buf) {
        const int kb = st * 32;
        uint32_t xh = smb + buf * GX_ST;
        uint32_t wh = xh + 10240;
#pragma unroll
        for (int p = 0; p < 4; p++) {
            int row = xrow + p * 32;
            uint32_t d = (uint32_t)(row * 80 + xch * 16);
            cp16(xh + d, &g_xh[(size_t)(m0 + row) * INF + kb + xch * 8]);
        }
#pragma unroll
        for (int p = 0; p < 2; p++) {
            int row = xrow + p * 32;
            uint32_t d = (uint32_t)(row * 80 + xch * 16);
            cp16(wh + d, &g_wh[(size_t)(n0 + row) * INF + kb + xch * 8]);
        }
        asm volatile("cp.async.commit_group;" ::: "memory");
    };

    stage(0, 0);
#pragma unroll 1
    for (int st = 0; st < INF / 32; st++) {
        const int buf = st & 1;
        if (st + 1 < INF / 32) {
            stage(st + 1, buf ^ 1);
            asm volatile("cp.async.wait_group 1;" ::: "memory");
        } else {
            asm volatile("cp.async.wait_group 0;" ::: "memory");
        }
        __syncthreads();
        uint32_t xh = smb + buf * GX_ST;
        uint32_t wh = xh + 10240;
#pragma unroll
        for (int ks = 0; ks < 2; ks++) {
            unsigned axh[2][4];
#pragma unroll
            for (int mf = 0; mf < 2; mf++) {
                ldm4(xh + (wm + mf * 16 + arow) * 80 + ks * 32 + ahalf * 16,
                     axh[mf][0], axh[mf][1], axh[mf][2], axh[mf][3]);
            }
#pragma unroll
            for (int f = 0; f < 4; f++) {
                uint32_t ba = (uint32_t)((f * 16 + brow_off) * 80 + ks * 32 + bkh * 16);
                unsigned bhf[4];
                ldm4(wh + ba, bhf[0], bhf[1], bhf[2], bhf[3]);
#pragma unroll
                for (int g = 0; g < 2; g++) {
#pragma unroll
                    for (int mf = 0; mf < 2; mf++) {
                        mma16816(acc[f * 2 + g][mf],
                                 axh[mf][0], axh[mf][1], axh[mf][2], axh[mf][3],
                                 bhf[2 * g], bhf[2 * g + 1]);
                    }
                }
            }
        }
        __syncthreads();
    }

    const int qc2 = (lane & 3) * 2;
    float dot[4][2];
#pragma unroll
    for (int r = 0; r < 4; r++) { dot[r][0] = 0.f; dot[r][1] = 0.f; }

#pragma unroll
    for (int f = 0; f < 8; f++) {
        int col = f * 8 + qc2;
        float2 bv = *(const float2*)&b[n0 + col];
        float4 awv = *(const float4*)&aw[hd * 128 + col * 2];
#pragma unroll
        for (int mf = 0; mf < 2; mf++) {
            float* C = acc[f][mf];
            int m = m0 + wm + mf * 16 + (lane >> 2);
            float c0 = C[0] + bv.x, c1 = C[1] + bv.y;
            float c2 = C[2] + bv.x, c3 = C[3] + bv.y;
            *(unsigned*)&g_hb[(size_t)(hd * NN + m) * 64 + col] = pack_f16x2(c1, c0);
            *(unsigned*)&g_hb[(size_t)(hd * NN + m + 8) * 64 + col] = pack_f16x2(c3, c2);
            dot[mf * 2][0] += c0 * awv.x + c1 * awv.z;
            dot[mf * 2][1] += c0 * awv.y + c1 * awv.w;
            dot[mf * 2 + 1][0] += c2 * awv.x + c3 * awv.z;
            dot[mf * 2 + 1][1] += c2 * awv.y + c3 * awv.w;
        }
    }
#pragma unroll
    for (int off = 1; off <= 2; off <<= 1)
#pragma unroll
        for (int r = 0; r < 4; r++) {
            dot[r][0] += __shfl_xor_sync(0xffffffffu, dot[r][0], off);
            dot[r][1] += __shfl_xor_sync(0xffffffffu, dot[r][1], off);
        }
    float a1loc = fmaxf(fmaxf(dot[0][1], dot[1][1]), fmaxf(dot[2][1], dot[3][1]));
    if ((lane & 3) == 0) {
        int mbase = m0 + wm + (lane >> 2);
        g_a0a1[hd * NN + mbase] = make_float2(dot[0][0], dot[0][1]);
        g_a0a1[hd * NN + mbase + 8] = make_float2(dot[1][0], dot[1][1]);
        g_a0a1[hd * NN + mbase + 16] = make_float2(dot[2][0], dot[2][1]);
        g_a0a1[hd * NN + mbase + 24] = make_float2(dot[3][0], dot[3][1]);
    }
#pragma unroll
    for (int off = 16; off > 0; off >>= 1)
        a1loc = fmaxf(a1loc, __shfl_xor_sync(0xffffffffu, a1loc, off));
    if (lane == 0) atomicMax(&g_a1max[hd], fkey(a1loc));
}

// =====================================================================
// Kernel B2: scaled tables (both sides fp16-safe)
// =====================================================================
__global__ __launch_bounds__(256) void param2_kernel() {
    int g = blockIdx.x * 256 + threadIdx.x;
    if (g >= H * NN) return;
    int hd = g / NN;
    int i = g - hd * NN;
    float2 a = g_a0a1[g];
    float a1max = funkey(g_a1max[hd]);
    float z = a.x + a1max;
    float sl = (z > 0.f) ? z : 0.2f * z;
    float uh = ECAP * expf(a.x - sl + a1max);
    float u5h = ECAP * expf(0.2f * a.x - sl + 0.2f * a1max);
    g_ai2[g] = make_float2(uh, u5h);
    unsigned short vv = __half_as_ushort(__float2half_rn(expf(a.y - a1max)));
    unsigned short v5 = __half_as_ushort(__float2half_rn(expf(0.2f * (a.y - a1max))));
    unsigned short* dst = (unsigned short*)&g_ajph[hd * (NN / 2) + (i >> 1)];
    int o = i & 1;
    dst[o] = vv;
    dst[2 + o] = v5;
}

// =====================================================================
// Kernel C: adj -> nibble-permuted bitmask, cp.async staging
// (no LDG->reg->STS round-trip; DMA queues all transfers immediately)
// =====================================================================
#define BSWZ(b) ((b) ^ (((b) >> 7 & 7) << 4))

__global__ __launch_bounds__(256) void bits_kernel(const int* __restrict__ adj) {
    __shared__ __align__(16) char stg[8][4096];
    const int tid = threadIdx.x;
    const int wp = tid >> 5;
    const int lane = tid & 31;
    const int w0 = blockIdx.x * 256 + wp * 32;
    const int4* src = (const int4*)(adj + (size_t)w0 * 32);
    char* sm = stg[wp];
    const uint32_t smw = smem_u32(sm);

#pragma unroll
    for (int c = 0; c < 8; c++) {
        unsigned lb = (unsigned)(c * 512 + lane * 16);
        cp16(smw + BSWZ(lb), src + c * 32 + lane);
    }
    asm volatile("cp.async.commit_group;" ::: "memory");
    asm volatile("cp.async.wait_group 0;" ::: "memory");
    __syncwarp();

    int v[32];
#pragma unroll
    for (int c = 0; c < 8; c++) {
        unsigned lb = (unsigned)(lane * 128 + c * 16);
        int4 q = *(const int4*)(sm + BSWZ(lb));
        v[c * 4 + 0] = q.x;
        v[c * 4 + 1] = q.y;
        v[c * 4 + 2] = q.z;
        v[c * 4 + 3] = q.w;
    }
    unsigned word = 0;
#pragma unroll
    for (int hb = 0; hb < 2; hb++) {
#pragma unroll
        for (int n = 0; n < 4; n++) {
            int b = hb * 16 + 2 * n;
            unsigned nib = (unsigned)(v[b] + 2 * v[b + 1] + 4 * v[b + 8] + 8 * v[b + 9]);
            word |= nib << (hb * 16 + n * 4);
        }
    }
    g_bits[w0 + lane] = word;
}

// =====================================================================
// Kernel D: fp16 HMMA attention (R14 winner: occ 3, register masks).
// =====================================================================
#define ONESF16 0x3C003C00u

__global__ __launch_bounds__(128, 3) void attn_kernel(float* __restrict__ out) {
    __shared__ __align__(16) char  sB[2][16384];
    __shared__ __align__(16) uint2 sAjp[2][64];
    __shared__ __align__(16) uint2 sLut[16];

    const int tid = threadIdx.x;
    const int wid = tid >> 5;
    const int lane = tid & 31;
    const int hd = blockIdx.y;
    const int i0 = blockIdx.x * 128;
    const int gr = lane >> 2;
    const int l3 = lane & 3;
    const int mb = wid * 32;

    const uint32_t smB = smem_u32(&sB[0][0]);
    const uint32_t smA = smem_u32(&sAjp[0][0]);

    if (tid < 16) {
        unsigned m01 = ((tid & 1) ? 0x0000FFFFu : 0u) | ((tid & 2) ? 0xFFFF0000u : 0u);
        unsigned m89 = ((tid & 4) ? 0x0000FFFFu : 0u) | ((tid & 8) ? 0xFFFF0000u : 0u);
        sLut[tid] = make_uint2(m01, m89);
    }

    uint32_t sdst[8];
#pragma unroll
    for (int p = 0; p < 8; p++) {
        int idx = tid + p * 128;
        int sj = idx >> 3, sc = idx & 7;
        sdst[p] = (uint32_t)(sj * 128 + ((sc ^ (sj & 7)) << 4));
    }
    const char* srcH = (const char*)(g_hb + (size_t)hd * NN * 64);
    const uint2* srcA = &g_ajph[hd * (NN / 2)];

    const int lg = lane >> 3, lr = lane & 7;
    const int joff = (lg & 1) * 8 + lr;
    const int nsel = lg >> 1;
    const uint32_t lmb = (uint32_t)(joff * 128);
    const int jm = joff & 7;

    unsigned uu[4], u5[4];
#pragma unroll
    for (int r = 0; r < 4; r++) {
        float2 a = g_ai2[hd * NN + i0 + mb + gr + r * 8];
        uu[r] = pack_f16x2(a.x, a.x);
        u5[r] = pack_f16x2(a.y, a.y);
    }
    const uint4* mrow[4];
#pragma unroll
    for (int r = 0; r < 4; r++)
        mrow[r] = (const uint4*)(g_bits + (size_t)(i0 + mb + gr + r * 8) * NW);

    float accA[8][4], accB[8][4], accSA[4], accSB[4];
#pragma unroll
    for (int n = 0; n < 8; n++)
#pragma unroll
        for (int c = 0; c < 4; c++) { accA[n][c] = 0.f; accB[n][c] = 0.f; }
#pragma unroll
    for (int c = 0; c < 4; c++) { accSA[c] = 0.f; accSB[c] = 0.f; }

    {
#pragma unroll
        for (int p = 0; p < 8; p++)
            cp16(smB + sdst[p], srcH + (size_t)(tid + p * 128) * 16);
        if (tid < 32) cp16(smA + tid * 16, srcA + tid * 2);
        asm volatile("cp.async.commit_group;" ::: "memory");
    }

#pragma unroll 1
    for (int jt = 0; jt < NT; jt++) {
        const int s = jt & 1;

        unsigned mw[4][4];
#pragma unroll
        for (int r = 0; r < 4; r++) {
            uint4 t = mrow[r][jt];
            mw[r][0] = t.x; mw[r][1] = t.y; mw[r][2] = t.z; mw[r][3] = t.w;
        }

        if (jt + 1 < NT) {
            uint32_t bh = smB + (s ^ 1) * 16384;
#pragma unroll
            for (int p = 0; p < 8; p++)
                cp16(bh + sdst[p],
                     srcH + (size_t)(jt + 1) * 16384 + (size_t)(tid + p * 128) * 16);
            if (tid < 32) cp16(smA + (s ^ 1) * 512 + tid * 16,
                               srcA + (jt + 1) * 64 + tid * 2);
            asm volatile("cp.async.commit_group;" ::: "memory");
            asm volatile("cp.async.wait_group 1;" ::: "memory");
        } else {
            asm volatile("cp.async.wait_group 0;" ::: "memory");
        }
        __syncthreads();

        const uint32_t bh = smB + s * 16384;
        const uint2* ajb = &sAjp[s][0];

#pragma unroll
        for (int kk = 0; kk < 8; kk++) {
            uint2 va = ajb[kk * 8 + l3];
            uint2 vb = ajb[kk * 8 + 4 + l3];

            unsigned ah[4][2];
#pragma unroll
            for (int r = 0; r < 4; r++) {
                unsigned nib = (mw[r][kk >> 1] >> ((kk & 1) * 16 + l3 * 4)) & 15u;
                uint2 mk = sLut[nib];
                ah[r][0] = hmax2(hmul2(uu[r], va.x), hmul2(u5[r], va.y)) & mk.x;
                ah[r][1] = hmax2(hmul2(uu[r], vb.x), hmul2(u5[r], vb.y)) & mk.y;
            }

            mma16816(accSA, ah[0][0], ah[1][0], ah[0][1], ah[1][1], ONESF16, ONESF16);
            mma16816(accSB, ah[2][0], ah[3][0], ah[2][1], ah[3][1], ONESF16, ONESF16);

#pragma unroll
            for (int nh = 0; nh < 2; nh++) {
                const int nb0 = nh * 32, nb1 = nh * 32 + 16;
                uint32_t a0 = bh + kk * 2048 + lmb + ((((nb0 >> 3) + nsel) ^ jm) << 4);
                uint32_t a1 = bh + kk * 2048 + lmb + ((((nb1 >> 3) + nsel) ^ jm) << 4);
                unsigned t[8];
                ldm4t(a0, t[0], t[1], t[2], t[3]);
                ldm4t(a1, t[4], t[5], t[6], t[7]);
#pragma unroll
                for (int q = 0; q < 4; q++) {
                    mma16816(accA[nh * 4 + q], ah[0][0], ah[1][0], ah[0][1], ah[1][1],
                             t[2 * q], t[2 * q + 1]);
                    mma16816(accB[nh * 4 + q], ah[2][0], ah[3][0], ah[2][1], ah[3][1],
                             t[2 * q], t[2 * q + 1]);
                }
            }
        }
        __syncthreads();
    }

    float inv[4];
    inv[0] = (accSA[0] > 0.f) ? (1.0f / accSA[0]) : 0.f;
    inv[1] = (accSA[2] > 0.f) ? (1.0f / accSA[2]) : 0.f;
    inv[2] = (accSB[0] > 0.f) ? (1.0f / accSB[0]) : 0.f;
    inv[3] = (accSB[2] > 0.f) ? (1.0f / accSB[2]) : 0.f;

    const int qc = l3 * 2;
#pragma unroll
    for (int f = 0; f < 2; f++) {
        float (*A)[4] = f ? accB : accA;
        float* b0 = out + (size_t)(i0 + mb + gr + f * 16) * OUTF + hd * 64 + qc;
        float* b1 = out + (size_t)(i0 + mb + gr + f * 16 + 8) * OUTF + hd * 64 + qc;
        float i0v = inv[f * 2], i1v = inv[f * 2 + 1];
#pragma unroll
        for (int nt = 0; nt < 8; nt++) {
            *(float2*)(b0 + nt * 8) = make_float2(A[nt][0] * i0v, A[nt][1] * i0v);
            *(float2*)(b1 + nt * 8) = make_float2(A[nt][2] * i1v, A[nt][3] * i1v);
        }
    }
}

// =====================================================================
extern "C" void kernel_launch(void* const* d_in, const int* in_sizes, int n_in,
                              void* d_out, int out_size) {
    const float* x = (const float*)d_in[0];
    const int* adj = (const int*)d_in[1];
    const float* W = (const float*)d_in[2];
    const float* b = (const float*)d_in[3];
    const float* aw = (const float*)d_in[4];
    float* out = (float*)d_out;

    cudaFuncSetAttribute(gemm_h_kernel, cudaFuncAttributeMaxDynamicSharedMemorySize,
                         GX_TOT);

    cvt_kernel<<<(NN * INF / 4 + OUTF * INF / 4 + 255) / 256, 256>>>(x, W);
    gemm_h_kernel<<<dim3(NN / 128, H), 128, GX_TOT>>>(b, aw);
    param2_kernel<<<(H * NN + 255) / 256, 256>>>();
    bits_kernel<<<NN * NW / 256, 256>>>(adj);
    attn_kernel<<<dim3(NN / 128, H), 128>>>(out);
}